// round 5
// baseline (speedup 1.0000x reference)
#include <cuda_runtime.h>
#include <cuda_bf16.h>

// Top-10% mask via sampled-pruned radix select; both matrices concurrent.
// S0: sample histogram (1/64 of data) -> conservative lower bin L0.
// S1: 8192-bin histogram of bits 29..17, atomics only for keys >= L0 (~13%).
// S2: 2-block scan in pruned prefix space -> coarse bin + in-bin rank
//     (fail flag + rescue kernel if the sample bound was wrong).
// S3: mask write + compact threshold-bin candidates (~131K/matrix).
// S4: merged candidate refinement (bits 16..7 then 6..0) -> exact T + z.
// S5: zero candidates < T, collect == T; last block per matrix does the
//     stable argsort tie fixup (zero first z equals by ascending index).

#define NB1      8192
#define SHIFT1   17
#define CAND_CAP 262144u
#define BLK_CAP  1024
#define EQ_CAP   8192

__device__ unsigned g_hist[2][NB1];
__device__ unsigned g_shist[2][NB1];
__device__ unsigned g_L0key[2];
__device__ unsigned g_binT[2];
__device__ unsigned g_rank[2];
__device__ unsigned g_keyT[2];
__device__ unsigned g_fail[2];
__device__ unsigned g_done[2];
__device__ unsigned g_cand_idx[2][CAND_CAP];
__device__ unsigned g_cand_key[2][CAND_CAP];
__device__ unsigned g_cand_cnt[2];
__device__ unsigned g_eq[2][EQ_CAP];
__device__ unsigned g_eq_cnt[2];

__device__ __forceinline__ unsigned abskey(float v) {
    return __float_as_uint(v) & 0x7FFFFFFFu;
}

// Block-wide (1024 thr) select over NB1 bins: rank = S - sub (ascending).
// On success: *sel = bin, *res = in-bin ascending offset, *ok = true.
__device__ __forceinline__ void block_select8(const unsigned* __restrict__ hist,
                                              unsigned sub, unsigned* sel,
                                              unsigned* res, bool* ok) {
    __shared__ unsigned tot[1024];
    __shared__ unsigned s_sel, s_res;
    const int t = threadIdx.x;
    if (t == 0) { s_sel = 0; s_res = 0; }
    unsigned loc[8];
    unsigned sum = 0;
    #pragma unroll
    for (int i = 0; i < 8; i++) { loc[i] = hist[t * 8 + i]; sum += loc[i]; }
    tot[t] = sum;
    __syncthreads();
    for (int off = 1; off < 1024; off <<= 1) {
        unsigned x = (t >= off) ? tot[t - off] : 0u;
        __syncthreads();
        tot[t] += x;
        __syncthreads();
    }
    unsigned S = tot[1023];
    bool good = (S >= sub);
    unsigned rank = S - sub;          // valid only if good
    unsigned run = tot[t] - sum;      // exclusive prefix
    if (good) {
        #pragma unroll
        for (int i = 0; i < 8; i++) {
            if (run <= rank && rank < run + loc[i]) { s_sel = t * 8 + i; s_res = rank - run; }
            run += loc[i];
        }
    }
    __syncthreads();
    *sel = s_sel; *res = s_res; *ok = good;
}

__global__ void reset_kernel(unsigned j) {
    int tid = blockIdx.x * blockDim.x + threadIdx.x;
    int stride = gridDim.x * blockDim.x;
    for (int i = tid; i < 2 * NB1; i += stride) {
        ((unsigned*)g_hist)[i] = 0;
        ((unsigned*)g_shist)[i] = 0;
    }
    if (tid < 2) {
        g_rank[tid] = j;
        g_cand_cnt[tid] = 0;
        g_eq_cnt[tid] = 0;
        g_fail[tid] = 0;
        g_done[tid] = 0;
    }
}

// Histogram the first n4s float4 chunks of each matrix (sample).
__global__ void sample_hist_kernel(const float4* __restrict__ A,
                                   const float4* __restrict__ B, int n4s) {
    __shared__ unsigned sh[NB1];
    for (int i = threadIdx.x; i < NB1; i += blockDim.x) sh[i] = 0;
    __syncthreads();
    const int m = blockIdx.x & 1;
    const float4* __restrict__ in = m ? B : A;
    int stride = (gridDim.x >> 1) * blockDim.x;
    for (int i = (blockIdx.x >> 1) * blockDim.x + threadIdx.x; i < n4s; i += stride) {
        float4 v = in[i];
        atomicAdd(&sh[min(abskey(v.x) >> SHIFT1, (unsigned)(NB1 - 1))], 1u);
        atomicAdd(&sh[min(abskey(v.y) >> SHIFT1, (unsigned)(NB1 - 1))], 1u);
        atomicAdd(&sh[min(abskey(v.z) >> SHIFT1, (unsigned)(NB1 - 1))], 1u);
        atomicAdd(&sh[min(abskey(v.w) >> SHIFT1, (unsigned)(NB1 - 1))], 1u);
    }
    __syncthreads();
    for (int i = threadIdx.x; i < NB1; i += blockDim.x) {
        unsigned c = sh[i];
        if (c) atomicAdd(&g_shist[m][i], c);
    }
}

// 2 blocks: pick L0 = bin at sampled suffix-count C from the top.
__global__ void sample_scan_kernel(unsigned C) {
    const int m = blockIdx.x;
    unsigned sel, res; bool ok;
    block_select8(g_shist[m], C, &sel, &res, &ok);
    if (threadIdx.x == 0) g_L0key[m] = ok ? (sel << SHIFT1) : 0u;
}

// Full read; atomics only for keys >= L0.
__global__ void hist1_kernel(const float4* __restrict__ A,
                             const float4* __restrict__ B, int n4) {
    __shared__ unsigned sh[NB1];
    for (int i = threadIdx.x; i < NB1; i += blockDim.x) sh[i] = 0;
    __syncthreads();
    const int m = blockIdx.x & 1;
    const float4* __restrict__ in = m ? B : A;
    const unsigned L0 = g_L0key[m];
    int stride = (gridDim.x >> 1) * blockDim.x;
    for (int i = (blockIdx.x >> 1) * blockDim.x + threadIdx.x; i < n4; i += stride) {
        float4 v = in[i];
        unsigned k;
        k = abskey(v.x); if (k >= L0) atomicAdd(&sh[min(k >> SHIFT1, (unsigned)(NB1 - 1))], 1u);
        k = abskey(v.y); if (k >= L0) atomicAdd(&sh[min(k >> SHIFT1, (unsigned)(NB1 - 1))], 1u);
        k = abskey(v.z); if (k >= L0) atomicAdd(&sh[min(k >> SHIFT1, (unsigned)(NB1 - 1))], 1u);
        k = abskey(v.w); if (k >= L0) atomicAdd(&sh[min(k >> SHIFT1, (unsigned)(NB1 - 1))], 1u);
    }
    __syncthreads();
    for (int i = threadIdx.x; i < NB1; i += blockDim.x) {
        unsigned c = sh[i];
        if (c) atomicAdd(&g_hist[m][i], c);
    }
}

// 2 blocks: select in pruned prefix space with rank = S - target_top.
__global__ void scan1_kernel(unsigned target_top) {
    const int m = blockIdx.x;
    unsigned sel, res; bool ok;
    block_select8(g_hist[m], target_top, &sel, &res, &ok);
    if (threadIdx.x == 0) {
        if (ok) { g_binT[m] = sel; g_rank[m] = res; }
        else    { g_fail[m] = 1; }  // g_rank stays j
    }
}

// 2 blocks; only runs the slow path if the sample bound failed (never, in
// practice). Completes g_hist with the complement (keys < L0), reselects.
__global__ void rescue_kernel(const float4* __restrict__ A,
                              const float4* __restrict__ B, int n4,
                              unsigned target_top) {
    const int m = blockIdx.x;
    if (!g_fail[m]) return;
    const float4* __restrict__ in = m ? B : A;
    const unsigned L0 = g_L0key[m];
    for (int i = threadIdx.x; i < n4; i += blockDim.x) {
        float4 v = in[i];
        unsigned k;
        k = abskey(v.x); if (k < L0) atomicAdd(&g_hist[m][min(k >> SHIFT1, (unsigned)(NB1 - 1))], 1u);
        k = abskey(v.y); if (k < L0) atomicAdd(&g_hist[m][min(k >> SHIFT1, (unsigned)(NB1 - 1))], 1u);
        k = abskey(v.z); if (k < L0) atomicAdd(&g_hist[m][min(k >> SHIFT1, (unsigned)(NB1 - 1))], 1u);
        k = abskey(v.w); if (k < L0) atomicAdd(&g_hist[m][min(k >> SHIFT1, (unsigned)(NB1 - 1))], 1u);
    }
    __threadfence();
    __syncthreads();
    unsigned sel, res; bool ok;
    block_select8(g_hist[m], target_top, &sel, &res, &ok);
    if (threadIdx.x == 0) { g_binT[m] = sel; g_rank[m] = res; }
}

__global__ void mask_kernel(const float4* __restrict__ A,
                            const float4* __restrict__ B,
                            float4* __restrict__ out, int n4) {
    __shared__ unsigned s_idx[BLK_CAP];
    __shared__ unsigned s_key[BLK_CAP];
    __shared__ unsigned s_cnt, s_base;
    if (threadIdx.x == 0) s_cnt = 0;
    __syncthreads();
    const int m = blockIdx.x & 1;
    const float4* __restrict__ in = m ? B : A;
    float4* __restrict__ dst = out + (size_t)m * (size_t)n4;
    const unsigned binT = g_binT[m];
    const unsigned keyLo = binT << SHIFT1;
    const unsigned keyHi = (binT + 1 < NB1) ? ((binT + 1) << SHIFT1) : 0xFFFFFFFFu;
    const int stride = (gridDim.x >> 1) * blockDim.x;
    int i0 = (blockIdx.x >> 1) * blockDim.x + threadIdx.x;
    for (int i = i0; i < n4; i += 2 * stride) {
        int i2 = i + stride;
        float4 v0 = in[i];
        float4 v1 = (i2 < n4) ? in[i2] : make_float4(0.f, 0.f, 0.f, 0.f);
        float4 r0, r1;
        unsigned b0 = ((unsigned)i) << 2;
        unsigned b1 = ((unsigned)i2) << 2;
        unsigned k;

        k = abskey(v0.x); r0.x = (k >= keyLo) ? 1.0f : 0.0f;
        if (k >= keyLo && k < keyHi) { unsigned p = atomicAdd(&s_cnt, 1u); if (p < BLK_CAP) { s_idx[p] = b0;     s_key[p] = k; } }
        k = abskey(v0.y); r0.y = (k >= keyLo) ? 1.0f : 0.0f;
        if (k >= keyLo && k < keyHi) { unsigned p = atomicAdd(&s_cnt, 1u); if (p < BLK_CAP) { s_idx[p] = b0 + 1; s_key[p] = k; } }
        k = abskey(v0.z); r0.z = (k >= keyLo) ? 1.0f : 0.0f;
        if (k >= keyLo && k < keyHi) { unsigned p = atomicAdd(&s_cnt, 1u); if (p < BLK_CAP) { s_idx[p] = b0 + 2; s_key[p] = k; } }
        k = abskey(v0.w); r0.w = (k >= keyLo) ? 1.0f : 0.0f;
        if (k >= keyLo && k < keyHi) { unsigned p = atomicAdd(&s_cnt, 1u); if (p < BLK_CAP) { s_idx[p] = b0 + 3; s_key[p] = k; } }
        dst[i] = r0;

        if (i2 < n4) {
            k = abskey(v1.x); r1.x = (k >= keyLo) ? 1.0f : 0.0f;
            if (k >= keyLo && k < keyHi) { unsigned p = atomicAdd(&s_cnt, 1u); if (p < BLK_CAP) { s_idx[p] = b1;     s_key[p] = k; } }
            k = abskey(v1.y); r1.y = (k >= keyLo) ? 1.0f : 0.0f;
            if (k >= keyLo && k < keyHi) { unsigned p = atomicAdd(&s_cnt, 1u); if (p < BLK_CAP) { s_idx[p] = b1 + 1; s_key[p] = k; } }
            k = abskey(v1.z); r1.z = (k >= keyLo) ? 1.0f : 0.0f;
            if (k >= keyLo && k < keyHi) { unsigned p = atomicAdd(&s_cnt, 1u); if (p < BLK_CAP) { s_idx[p] = b1 + 2; s_key[p] = k; } }
            k = abskey(v1.w); r1.w = (k >= keyLo) ? 1.0f : 0.0f;
            if (k >= keyLo && k < keyHi) { unsigned p = atomicAdd(&s_cnt, 1u); if (p < BLK_CAP) { s_idx[p] = b1 + 3; s_key[p] = k; } }
            dst[i2] = r1;
        }
    }
    __syncthreads();
    if (threadIdx.x == 0) {
        unsigned c = min(s_cnt, (unsigned)BLK_CAP);
        s_cnt = c;
        s_base = atomicAdd(&g_cand_cnt[m], c);
    }
    __syncthreads();
    unsigned c = s_cnt, bpos = s_base;
    for (unsigned p = threadIdx.x; p < c; p += blockDim.x) {
        unsigned gp = bpos + p;
        if (gp < CAND_CAP) { g_cand_idx[m][gp] = s_idx[p]; g_cand_key[m][gp] = s_key[p]; }
    }
}

// 2 blocks: refine bits 16..7 (1024 bins) then 6..0 (128 bins) -> T, z.
__global__ void candAB_kernel() {
    __shared__ unsigned h[1024];
    __shared__ unsigned s_sel, s_rank;
    const int m = blockIdx.x;
    const int t = threadIdx.x;
    const unsigned* __restrict__ keys = g_cand_key[m];
    unsigned cnt = min(g_cand_cnt[m], CAND_CAP);
    unsigned rank = g_rank[m];

    // phase A: bits 16..7
    h[t] = 0;
    __syncthreads();
    for (unsigned c = t; c < cnt; c += 1024)
        atomicAdd(&h[(keys[c] >> 7) & 1023u], 1u);
    __syncthreads();
    unsigned v = h[t];
    for (int off = 1; off < 1024; off <<= 1) {
        unsigned x = (t >= off) ? h[t - off] : 0u;
        __syncthreads();
        h[t] += x;
        __syncthreads();
    }
    {
        unsigned incl = h[t], before = incl - v;
        if (before <= rank && rank < incl) { s_sel = t; s_rank = rank - before; }
    }
    __syncthreads();
    const unsigned selA = s_sel;
    rank = s_rank;
    __syncthreads();

    // phase B: bits 6..0 among candidates matching selA
    if (t < 128) h[t] = 0;
    __syncthreads();
    for (unsigned c = t; c < cnt; c += 1024) {
        unsigned k = keys[c];
        if (((k >> 7) & 1023u) == selA) atomicAdd(&h[k & 127u], 1u);
    }
    __syncthreads();
    v = (t < 128) ? h[t] : 0u;
    for (int off = 1; off < 128; off <<= 1) {
        unsigned x = (t < 128 && t >= off) ? h[t - off] : 0u;
        __syncthreads();
        if (t < 128) h[t] += x;
        __syncthreads();
    }
    if (t < 128) {
        unsigned incl = h[t], before = incl - v;
        if (before <= rank && rank < incl) { s_sel = t; s_rank = rank - before; }
    }
    __syncthreads();
    if (t == 0) {
        g_keyT[m] = (g_binT[m] << SHIFT1) | (selA << 7) | s_sel;
        g_rank[m] = s_rank;   // z: # of T-equals (by ascending index) to zero
    }
}

// Multi-block: zero candidates < T, collect == T; last block per matrix
// performs the stable tie fixup.
__global__ void final_fixup_kernel(float* __restrict__ out, int n) {
    __shared__ unsigned s_last;
    const int m = blockIdx.x & 1;
    const unsigned nb = gridDim.x >> 1;
    float* __restrict__ dst = out + (size_t)m * (size_t)n;
    const unsigned T = g_keyT[m];
    unsigned cnt = min(g_cand_cnt[m], CAND_CAP);
    int stride = nb * blockDim.x;
    for (unsigned c = (blockIdx.x >> 1) * blockDim.x + threadIdx.x; c < cnt; c += stride) {
        unsigned k = g_cand_key[m][c];
        if (k < T) {
            dst[g_cand_idx[m][c]] = 0.0f;
        } else if (k == T) {
            unsigned p = atomicAdd(&g_eq_cnt[m], 1u);
            if (p < EQ_CAP) g_eq[m][p] = g_cand_idx[m][c];
        }
    }
    __threadfence();
    __syncthreads();
    if (threadIdx.x == 0)
        s_last = (atomicAdd(&g_done[m], 1u) == nb - 1u) ? 1u : 0u;
    __syncthreads();
    if (s_last) {
        __threadfence();
        unsigned eq = min(g_eq_cnt[m], (unsigned)EQ_CAP);
        unsigned z = g_rank[m];
        for (unsigned e = threadIdx.x; e < eq; e += blockDim.x) {
            unsigned idx = g_eq[m][e];
            unsigned c2 = 0;
            for (unsigned s = 0; s < eq; s++) c2 += (g_eq[m][s] < idx) ? 1u : 0u;
            if (c2 < z) dst[idx] = 0.0f;
        }
    }
}

extern "C" void kernel_launch(void* const* d_in, const int* in_sizes, int n_in,
                              void* d_out, int out_size) {
    const float* A = (const float*)d_in[0];
    const float* B = (const float*)d_in[1];
    float* out = (float*)d_out;

    int n = in_sizes[0];
    int n4 = n / 4;
    unsigned j = (unsigned)((1.0 - 0.1) * (double)n);  // mirrors int((1-k)*n)
    unsigned target_top = (unsigned)n - j;             // # of ones
    int n4s = n4 / 64;                                 // sample: 1/64 of data
    unsigned ns = (unsigned)n4s * 4u;
    // Sampled suffix-count bound with huge margin (~45 sigma)
    unsigned C = target_top / 64u + 8192u;
    if (C > ns) C = ns;

    reset_kernel<<<32, 1024>>>(j);
    sample_hist_kernel<<<64, 512>>>((const float4*)A, (const float4*)B, n4s);
    sample_scan_kernel<<<2, 1024>>>(C);
    hist1_kernel<<<2048, 512>>>((const float4*)A, (const float4*)B, n4);
    scan1_kernel<<<2, 1024>>>(target_top);
    rescue_kernel<<<2, 1024>>>((const float4*)A, (const float4*)B, n4, target_top);
    mask_kernel<<<2048, 512>>>((const float4*)A, (const float4*)B, (float4*)out, n4);
    candAB_kernel<<<2, 1024>>>();
    final_fixup_kernel<<<256, 256>>>(out, n);
}

// round 6
// speedup vs baseline: 1.0169x; 1.0169x over previous
#include <cuda_runtime.h>
#include <cuda_bf16.h>

// Single full-pass top-10% mask via sampled band + candidate refinement.
// S0: sample histogram (1/64 prefix) -> conservative band [Tlo, Thi) that
//     contains the true threshold key (13-sigma margin + bin rounding).
// S1: FUSED pass (the only full read+write): mask = (k >= Tlo) provisionally,
//     count k >= Thi (definite ones), compact band elements (key, idx).
// S2: three narrowing stages over candidates (2048-bin hist + last-block
//     scan fused via done-counter) -> exact threshold key T + tie residual z.
// S3: final pass over candidates: k<T -> 0, collect k==T; last block zeroes
//     the first z equals by ascending flat index (stable argsort semantics).
// S4: guarded rescue kernel (slow, single-block, provably correct) -- only
//     runs if any conservative bound failed; probability ~1e-39.

#define NB1      8192
#define SHIFT1   17
#define NCH      2048
#define CAND_CAP (1u << 20)
#define BLK_CAP  2048
#define EQ_CAP   8192

__device__ unsigned g_shist[2][NB1];
__device__ unsigned g_ch[2][NCH];
__device__ unsigned g_Tlo[2], g_Thi[2];
__device__ unsigned g_lo[2], g_span[2], g_rank[2];
__device__ unsigned g_hiCnt[2];
__device__ unsigned g_cand_idx[2][CAND_CAP];
__device__ unsigned g_cand_key[2][CAND_CAP];
__device__ unsigned g_cand_cnt[2];
__device__ unsigned g_fail[2];
__device__ unsigned g_done[2][4];
__device__ unsigned g_eq[2][EQ_CAP];
__device__ unsigned g_eq_cnt[2];

__device__ __forceinline__ unsigned abskey(float v) {
    return __float_as_uint(v) & 0x7FFFFFFFu;
}

__global__ void reset_kernel() {
    int tid = blockIdx.x * blockDim.x + threadIdx.x;
    int stride = gridDim.x * blockDim.x;
    for (int i = tid; i < 2 * NB1; i += stride) ((unsigned*)g_shist)[i] = 0;
    for (int i = tid; i < 2 * NCH; i += stride) ((unsigned*)g_ch)[i] = 0;
    if (tid < 2) {
        g_cand_cnt[tid] = 0;
        g_eq_cnt[tid] = 0;
        g_hiCnt[tid] = 0;
        g_fail[tid] = 0;
        for (int s = 0; s < 4; s++) g_done[tid][s] = 0;
    }
}

__global__ void sample_hist_kernel(const float4* __restrict__ A,
                                   const float4* __restrict__ B, int n4s) {
    __shared__ unsigned sh[NB1];
    for (int i = threadIdx.x; i < NB1; i += blockDim.x) sh[i] = 0;
    __syncthreads();
    const int m = blockIdx.x & 1;
    const float4* __restrict__ in = m ? B : A;
    int stride = (gridDim.x >> 1) * blockDim.x;
    for (int i = (blockIdx.x >> 1) * blockDim.x + threadIdx.x; i < n4s; i += stride) {
        float4 v = in[i];
        atomicAdd(&sh[min(abskey(v.x) >> SHIFT1, (unsigned)(NB1 - 1))], 1u);
        atomicAdd(&sh[min(abskey(v.y) >> SHIFT1, (unsigned)(NB1 - 1))], 1u);
        atomicAdd(&sh[min(abskey(v.z) >> SHIFT1, (unsigned)(NB1 - 1))], 1u);
        atomicAdd(&sh[min(abskey(v.w) >> SHIFT1, (unsigned)(NB1 - 1))], 1u);
    }
    __syncthreads();
    for (int i = threadIdx.x; i < NB1; i += blockDim.x) {
        unsigned c = sh[i];
        if (c) atomicAdd(&g_shist[m][i], c);
    }
}

// Block-wide (1024 thr) select over NB1 bins; rank = total - sub (ascending).
__device__ __forceinline__ unsigned block_select_nb1(const unsigned* __restrict__ hist,
                                                     unsigned sub) {
    __shared__ unsigned tot[1024];
    __shared__ unsigned s_sel;
    const int t = threadIdx.x;
    if (t == 0) s_sel = 0;
    unsigned loc[8];
    unsigned sum = 0;
    #pragma unroll
    for (int i = 0; i < 8; i++) { loc[i] = hist[t * 8 + i]; sum += loc[i]; }
    tot[t] = sum;
    __syncthreads();
    for (int off = 1; off < 1024; off <<= 1) {
        unsigned x = (t >= off) ? tot[t - off] : 0u;
        __syncthreads();
        tot[t] += x;
        __syncthreads();
    }
    unsigned S = tot[1023];
    if (S >= sub) {
        unsigned rank = S - sub;
        unsigned run = tot[t] - sum;
        #pragma unroll
        for (int i = 0; i < 8; i++) {
            if (run <= rank && rank < run + loc[i]) s_sel = t * 8 + i;
            run += loc[i];
        }
    }
    __syncthreads();
    unsigned r = s_sel;
    __syncthreads();
    return r;
}

// 2 blocks: band bins from sampled suffix counts (C_hi -> Tlo, C_lo -> Thi).
__global__ void sample_scan_kernel(unsigned C_lo, unsigned C_hi) {
    const int m = blockIdx.x;
    unsigned binLo = block_select_nb1(g_shist[m], C_hi);
    unsigned binHi = block_select_nb1(g_shist[m], C_lo);
    if (threadIdx.x == 0) {
        unsigned Tlo = binLo << SHIFT1;
        unsigned Thi = (binHi >= NB1 - 1) ? 0xFFFFFFFFu : ((binHi + 1u) << SHIFT1);
        g_Tlo[m] = Tlo;
        g_Thi[m] = Thi;
        g_lo[m] = Tlo;
        g_span[m] = Thi - Tlo;
    }
}

// THE full pass: provisional mask write + hi count + band compaction.
__global__ void fused_kernel(const float4* __restrict__ A,
                             const float4* __restrict__ B,
                             float4* __restrict__ out, int n4) {
    __shared__ unsigned s_idx[BLK_CAP];
    __shared__ unsigned s_key[BLK_CAP];
    __shared__ unsigned s_cnt, s_base, s_hi;
    if (threadIdx.x == 0) { s_cnt = 0; s_hi = 0; }
    __syncthreads();
    const int m = blockIdx.x & 1;
    const float4* __restrict__ in = m ? B : A;
    float4* __restrict__ dst = out + (size_t)m * (size_t)n4;
    const unsigned Tlo = g_Tlo[m];
    const unsigned Thi = g_Thi[m];
    unsigned hi = 0;
    const int stride = (gridDim.x >> 1) * blockDim.x;
    int i0 = (blockIdx.x >> 1) * blockDim.x + threadIdx.x;
    for (int i = i0; i < n4; i += 2 * stride) {
        int i2 = i + stride;
        float4 v0 = in[i];
        float4 v1 = (i2 < n4) ? in[i2] : make_float4(0.f, 0.f, 0.f, 0.f);
        float4 r0, r1;
        unsigned b0 = ((unsigned)i) << 2;
        unsigned b1 = ((unsigned)i2) << 2;
        unsigned k;

        k = abskey(v0.x); r0.x = (k >= Tlo) ? 1.0f : 0.0f; hi += (k >= Thi);
        if (k >= Tlo && k < Thi) { unsigned p = atomicAdd(&s_cnt, 1u); if (p < BLK_CAP) { s_idx[p] = b0;     s_key[p] = k; } }
        k = abskey(v0.y); r0.y = (k >= Tlo) ? 1.0f : 0.0f; hi += (k >= Thi);
        if (k >= Tlo && k < Thi) { unsigned p = atomicAdd(&s_cnt, 1u); if (p < BLK_CAP) { s_idx[p] = b0 + 1; s_key[p] = k; } }
        k = abskey(v0.z); r0.z = (k >= Tlo) ? 1.0f : 0.0f; hi += (k >= Thi);
        if (k >= Tlo && k < Thi) { unsigned p = atomicAdd(&s_cnt, 1u); if (p < BLK_CAP) { s_idx[p] = b0 + 2; s_key[p] = k; } }
        k = abskey(v0.w); r0.w = (k >= Tlo) ? 1.0f : 0.0f; hi += (k >= Thi);
        if (k >= Tlo && k < Thi) { unsigned p = atomicAdd(&s_cnt, 1u); if (p < BLK_CAP) { s_idx[p] = b0 + 3; s_key[p] = k; } }
        dst[i] = r0;

        if (i2 < n4) {
            k = abskey(v1.x); r1.x = (k >= Tlo) ? 1.0f : 0.0f; hi += (k >= Thi);
            if (k >= Tlo && k < Thi) { unsigned p = atomicAdd(&s_cnt, 1u); if (p < BLK_CAP) { s_idx[p] = b1;     s_key[p] = k; } }
            k = abskey(v1.y); r1.y = (k >= Tlo) ? 1.0f : 0.0f; hi += (k >= Thi);
            if (k >= Tlo && k < Thi) { unsigned p = atomicAdd(&s_cnt, 1u); if (p < BLK_CAP) { s_idx[p] = b1 + 1; s_key[p] = k; } }
            k = abskey(v1.z); r1.z = (k >= Tlo) ? 1.0f : 0.0f; hi += (k >= Thi);
            if (k >= Tlo && k < Thi) { unsigned p = atomicAdd(&s_cnt, 1u); if (p < BLK_CAP) { s_idx[p] = b1 + 2; s_key[p] = k; } }
            k = abskey(v1.w); r1.w = (k >= Tlo) ? 1.0f : 0.0f; hi += (k >= Thi);
            if (k >= Tlo && k < Thi) { unsigned p = atomicAdd(&s_cnt, 1u); if (p < BLK_CAP) { s_idx[p] = b1 + 3; s_key[p] = k; } }
            dst[i2] = r1;
        }
    }
    // reduce hi count
    for (int off = 16; off > 0; off >>= 1) hi += __shfl_down_sync(0xFFFFFFFFu, hi, off);
    if ((threadIdx.x & 31) == 0 && hi) atomicAdd(&s_hi, hi);
    __syncthreads();
    if (threadIdx.x == 0) {
        if (s_hi) atomicAdd(&g_hiCnt[m], s_hi);
        unsigned c = s_cnt;
        if (c > BLK_CAP) { atomicExch(&g_fail[m], 1u); c = BLK_CAP; }
        s_cnt = c;
        s_base = atomicAdd(&g_cand_cnt[m], c);
    }
    __syncthreads();
    unsigned c = s_cnt, bpos = s_base;
    for (unsigned p = threadIdx.x; p < c; p += blockDim.x) {
        unsigned gp = bpos + p;
        if (gp < CAND_CAP) { g_cand_idx[m][gp] = s_idx[p]; g_cand_key[m][gp] = s_key[p]; }
    }
}

// Narrowing stage over candidates: 2048-bin hist (all blocks) + last-block
// scan + interval update. grid 64 x 1024.
__global__ void stage_kernel(int stage, unsigned target_top) {
    __shared__ unsigned sh[NCH];
    __shared__ unsigned s_last, s_skip, s_rank, s_sel, s_res;
    const int m = blockIdx.x & 1;
    const unsigned nb = gridDim.x >> 1;
    const int t = threadIdx.x;
    if (g_fail[m]) return;
    const unsigned lo = g_lo[m];
    const unsigned span = g_span[m];
    if (span == 1) return;  // already resolved
    unsigned s = (span > (unsigned)NCH) ? (unsigned)(32 - __clz(span - 1) - 11) : 0u;

    for (int i = t; i < NCH; i += blockDim.x) sh[i] = 0;
    __syncthreads();
    unsigned cnt = min(g_cand_cnt[m], CAND_CAP);
    const unsigned* __restrict__ keys = g_cand_key[m];
    {
        unsigned stride = nb * blockDim.x;
        for (unsigned c = (blockIdx.x >> 1) * blockDim.x + t; c < cnt; c += stride) {
            unsigned d = keys[c] - lo;
            if (d < span) atomicAdd(&sh[d >> s], 1u);
        }
    }
    __syncthreads();
    for (int i = t; i < NCH; i += blockDim.x) {
        unsigned c = sh[i];
        if (c) atomicAdd(&g_ch[m][i], c);
    }
    __threadfence();
    __syncthreads();
    if (t == 0) s_last = (atomicAdd(&g_done[m][stage - 1], 1u) == nb - 1u) ? 1u : 0u;
    __syncthreads();
    if (!s_last) return;
    __threadfence();

    if (t == 0) {
        s_skip = 0;
        if (stage == 1) {
            unsigned hic = g_hiCnt[m];
            unsigned realcnt = g_cand_cnt[m];
            if (hic > target_top || hic + cnt < target_top || realcnt > CAND_CAP) {
                g_fail[m] = 1; s_skip = 1;
            } else {
                unsigned keep = target_top - hic;
                if (keep == 0) {
                    g_lo[m] = 0xFFFFFFFFu; g_span[m] = 1; g_rank[m] = 0;
                    s_skip = 1;
                } else {
                    s_rank = cnt - keep;
                }
            }
        } else {
            s_rank = g_rank[m];
        }
    }
    __syncthreads();
    if (s_skip) return;
    unsigned rank = s_rank;

    // scan 2048 bins (2 per thread) for ascending rank
    unsigned l0 = g_ch[m][2 * t], l1 = g_ch[m][2 * t + 1];
    __syncthreads();
    sh[t] = l0 + l1;
    __syncthreads();
    for (int off = 1; off < 1024; off <<= 1) {
        unsigned x = (t >= off) ? sh[t - off] : 0u;
        __syncthreads();
        sh[t] += x;
        __syncthreads();
    }
    unsigned run = sh[t] - (l0 + l1);
    if (run <= rank && rank < run + l0) { s_sel = 2 * t; s_res = rank - run; }
    else if (run + l0 <= rank && rank < run + l0 + l1) { s_sel = 2 * t + 1; s_res = rank - run - l0; }
    __syncthreads();
    if (t == 0) {
        g_lo[m] = lo + (s_sel << s);
        g_span[m] = 1u << s;
        g_rank[m] = s_res;
    }
    // clear g_ch for next stage
    for (int i = t; i < NCH; i += blockDim.x) g_ch[m][i] = 0;
}

// Final candidate pass + stable tie fixup (last block per matrix).
__global__ void final_fixup_kernel(float* __restrict__ out, int n) {
    __shared__ unsigned s_last;
    const int m = blockIdx.x & 1;
    const unsigned nb = gridDim.x >> 1;
    if (g_fail[m]) return;
    float* __restrict__ dst = out + (size_t)m * (size_t)n;
    const unsigned T = g_lo[m];
    unsigned cnt = min(g_cand_cnt[m], CAND_CAP);
    unsigned stride = nb * blockDim.x;
    for (unsigned c = (blockIdx.x >> 1) * blockDim.x + threadIdx.x; c < cnt; c += stride) {
        unsigned k = g_cand_key[m][c];
        if (k < T) {
            dst[g_cand_idx[m][c]] = 0.0f;
        } else if (k == T) {
            unsigned p = atomicAdd(&g_eq_cnt[m], 1u);
            if (p < EQ_CAP) g_eq[m][p] = g_cand_idx[m][c];
        }
    }
    __threadfence();
    __syncthreads();
    if (threadIdx.x == 0)
        s_last = (atomicAdd(&g_done[m][3], 1u) == nb - 1u) ? 1u : 0u;
    __syncthreads();
    if (!s_last) return;
    __threadfence();
    unsigned eq = g_eq_cnt[m];
    if (eq > EQ_CAP) { if (threadIdx.x == 0) g_fail[m] = 1; return; }
    unsigned z = g_rank[m];
    for (unsigned e = threadIdx.x; e < eq; e += blockDim.x) {
        unsigned idx = g_eq[m][e];
        unsigned c2 = 0;
        for (unsigned sdx = 0; sdx < eq; sdx++) c2 += (g_eq[m][sdx] < idx) ? 1u : 0u;
        if (c2 < z) dst[idx] = 0.0f;
    }
}

// Guarded rescue: single block per matrix, slow but unconditionally correct.
// Only executes if a conservative bound failed (probability ~1e-39).
__global__ void rescue_kernel(const float* __restrict__ A,
                              const float* __restrict__ B,
                              float* __restrict__ out, int n, unsigned target_top) {
    const int m = blockIdx.x;
    if (!g_fail[m]) return;
    const float* __restrict__ in = m ? B : A;
    float* __restrict__ dst = out + (size_t)m * (size_t)n;
    __shared__ unsigned sh[NB1];
    __shared__ unsigned s_lo, s_span, s_rank;
    const int t = threadIdx.x;

    // coarse: full 8192-bin hist
    for (int i = t; i < NB1; i += blockDim.x) sh[i] = 0;
    __syncthreads();
    for (int i = t; i < n; i += blockDim.x)
        atomicAdd(&sh[min(abskey(in[i]) >> SHIFT1, (unsigned)(NB1 - 1))], 1u);
    __syncthreads();
    if (t == 0) {
        unsigned rank = (unsigned)n - target_top;  // ascending rank of threshold elem
        unsigned run = 0, bin = 0;
        for (int i = 0; i < NB1; i++) {
            if (rank < run + sh[i]) { bin = i; rank -= run; break; }
            run += sh[i];
        }
        s_lo = (unsigned)bin << SHIFT1;
        s_span = (bin == NB1 - 1) ? (0xFFFFFFFFu - ((unsigned)bin << SHIFT1)) : (1u << SHIFT1);
        s_rank = rank;
    }
    __syncthreads();

    // narrow to exact key
    while (s_span > 1) {
        unsigned lo = s_lo, span = s_span;
        unsigned s = (span > (unsigned)NCH) ? (unsigned)(32 - __clz(span - 1) - 11) : 0u;
        __syncthreads();
        for (int i = t; i < NCH; i += blockDim.x) sh[i] = 0;
        __syncthreads();
        for (int i = t; i < n; i += blockDim.x) {
            unsigned d = abskey(in[i]) - lo;
            if (d < span) atomicAdd(&sh[d >> s], 1u);
        }
        __syncthreads();
        if (t == 0) {
            unsigned rank = s_rank, run = 0, bin = 0;
            for (int i = 0; i < NCH; i++) {
                if (rank < run + sh[i]) { bin = i; rank -= run; break; }
                run += sh[i];
            }
            s_lo = lo + (bin << s);
            s_span = 1u << s;
            s_rank = rank;
        }
        __syncthreads();
    }
    const unsigned T = s_lo;
    const unsigned z = s_rank;

    // write all non-equal elements in parallel
    for (int i = t; i < n; i += blockDim.x) {
        unsigned k = abskey(in[i]);
        if (k != T) dst[i] = (k > T) ? 1.0f : 0.0f;
    }
    __syncthreads();
    // serial stable tie-break for equals
    if (t == 0) {
        unsigned seen = 0;
        for (int i = 0; i < n; i++) {
            if (abskey(in[i]) == T) { dst[i] = (seen < z) ? 0.0f : 1.0f; seen++; }
        }
    }
}

extern "C" void kernel_launch(void* const* d_in, const int* in_sizes, int n_in,
                              void* d_out, int out_size) {
    const float* A = (const float*)d_in[0];
    const float* B = (const float*)d_in[1];
    float* out = (float*)d_out;

    int n = in_sizes[0];
    int n4 = n / 4;
    unsigned j = (unsigned)((1.0 - 0.1) * (double)n);  // mirrors int((1-k)*n)
    unsigned target_top = (unsigned)n - j;             // # of ones
    int n4s = n4 / 64;
    unsigned ns = (unsigned)n4s * 4u;
    unsigned k_s = target_top / 64u;
    unsigned margin = 2048u;
    unsigned C_hi = k_s + margin; if (C_hi > ns) C_hi = ns;
    unsigned C_lo = (k_s > margin) ? (k_s - margin) : 1u;

    reset_kernel<<<16, 1024>>>();
    sample_hist_kernel<<<64, 512>>>((const float4*)A, (const float4*)B, n4s);
    sample_scan_kernel<<<2, 1024>>>(C_lo, C_hi);
    fused_kernel<<<2048, 512>>>((const float4*)A, (const float4*)B, (float4*)out, n4);
    stage_kernel<<<64, 1024>>>(1, target_top);
    stage_kernel<<<64, 1024>>>(2, target_top);
    stage_kernel<<<64, 1024>>>(3, target_top);
    final_fixup_kernel<<<64, 256>>>(out, n);
    rescue_kernel<<<2, 1024>>>(A, B, out, n, target_top);
}

// round 7
// speedup vs baseline: 1.2721x; 1.2509x over previous
#include <cuda_runtime.h>
#include <cuda_bf16.h>

// Two-launch top-10% mask.
// K1 (mega): blocks 0-127 sample 1/64 -> 8192-bin hist -> conservative band
//            [Tlo,Thi) (13-sigma margins); other blocks spin on a flag; then
//            ALL blocks run the fused pass: provisional mask (k>=Tlo -> 1),
//            count k>=Thi, compact band elements (~400K/matrix).
// K2 (refine): 32 blocks/matrix with device grid-barriers: two narrowing
//            stages over candidates -> exact threshold key T + residual z;
//            final pass zeroes k<T and collects k==T; block 0 does the
//            stable argsort tie fixup (first z equals by ascending index);
//            guarded single-block rescue if any bound failed (p ~ 1e-39).
// State is self-cleaning across graph replays: K2 resets K1's state at its
// end; K1 resets K2's barrier counters at its start (ordering via launch
// boundary - avoids zero-while-spinning deadlock).

#define NB1      8192
#define SHIFT1   17
#define NCH      2048
#define CAND_CAP (1u << 20)
#define BLK_CAP  1024
#define EQ_CAP   8192

__device__ unsigned g_shist[2][NB1];
__device__ unsigned g_ch[2][2][NCH];
__device__ unsigned g_Tlo[2], g_Thi[2];
__device__ unsigned g_sdone[2];
__device__ unsigned g_ready[2];
__device__ unsigned g_cand_idx[2][CAND_CAP];
__device__ unsigned g_cand_key[2][CAND_CAP];
__device__ unsigned g_cand_cnt[2];
__device__ unsigned g_hiCnt[2];
__device__ unsigned g_fail[2];
__device__ unsigned g_bar[2][8];
__device__ unsigned g_eq[2][EQ_CAP];
__device__ unsigned g_eq_cnt[2];

__device__ __forceinline__ unsigned abskey(float v) {
    return __float_as_uint(v) & 0x7FFFFFFFu;
}

// 512-thread block select over NB1 bins: largest-suffix cut with count >= sub.
__device__ unsigned sel512(const unsigned* __restrict__ h, unsigned sub) {
    __shared__ unsigned tot[512];
    __shared__ unsigned ssel;
    const int t = threadIdx.x;
    if (t == 0) ssel = 0;
    unsigned loc[16], sum = 0;
    #pragma unroll
    for (int i = 0; i < 16; i++) { loc[i] = h[t * 16 + i]; sum += loc[i]; }
    tot[t] = sum;
    __syncthreads();
    for (int off = 1; off < 512; off <<= 1) {
        unsigned x = (t >= off) ? tot[t - off] : 0u;
        __syncthreads();
        tot[t] += x;
        __syncthreads();
    }
    unsigned S = tot[511];
    if (S >= sub) {
        unsigned rank = S - sub;
        unsigned run = tot[t] - sum;
        #pragma unroll
        for (int i = 0; i < 16; i++) {
            if (run <= rank && rank < run + loc[i]) ssel = (unsigned)(t * 16 + i);
            run += loc[i];
        }
    }
    __syncthreads();
    unsigned r = ssel;
    __syncthreads();
    return r;
}

__global__ void __launch_bounds__(512)
mega_kernel(const float4* __restrict__ A, const float4* __restrict__ B,
            float4* __restrict__ out, int n4, int chunk,
            unsigned C_lo, unsigned C_hi) {
    __shared__ unsigned sh[NB1];
    __shared__ unsigned s_idx[BLK_CAP];
    __shared__ unsigned s_key[BLK_CAP];
    __shared__ unsigned s_cnt, s_base, s_hi, s_flag;
    const int m = blockIdx.x & 1;
    const int t = threadIdx.x;

    // Reset K2's barrier counters for the NEXT refine launch (prev refine done).
    if (blockIdx.x == 0 && t < 16) ((unsigned*)g_bar)[t] = 0;

    // ---- sample phase (blocks 0..127; 64 per matrix) ----
    if (blockIdx.x < 128) {
        for (int i = t; i < NB1; i += 512) sh[i] = 0;
        __syncthreads();
        const float4* __restrict__ in = m ? B : A;
        int sbl = blockIdx.x >> 1;               // 0..63
        int beg = sbl * chunk, end = beg + chunk;
        for (int i = beg + t; i < end; i += 512) {
            float4 v = in[i];
            atomicAdd(&sh[min(abskey(v.x) >> SHIFT1, (unsigned)(NB1 - 1))], 1u);
            atomicAdd(&sh[min(abskey(v.y) >> SHIFT1, (unsigned)(NB1 - 1))], 1u);
            atomicAdd(&sh[min(abskey(v.z) >> SHIFT1, (unsigned)(NB1 - 1))], 1u);
            atomicAdd(&sh[min(abskey(v.w) >> SHIFT1, (unsigned)(NB1 - 1))], 1u);
        }
        __syncthreads();
        for (int i = t; i < NB1; i += 512) {
            unsigned c = sh[i];
            if (c) atomicAdd(&g_shist[m][i], c);
        }
        __threadfence();
        if (t == 0) s_flag = (atomicAdd(&g_sdone[m], 1u) == 63u) ? 1u : 0u;
        __syncthreads();
        if (s_flag) {
            __threadfence();
            unsigned binLo = sel512(g_shist[m], C_hi);
            unsigned binHi = sel512(g_shist[m], C_lo);
            if (t == 0) {
                unsigned Tlo = binLo << SHIFT1;
                unsigned Thi = (binHi >= NB1 - 1) ? 0xFFFFFFFFu
                                                  : ((binHi + 1u) << SHIFT1);
                g_Tlo[m] = Tlo;
                g_Thi[m] = Thi;
                __threadfence();
                atomicExch(&g_ready[m], 1u);
            }
        }
    }

    // ---- wait for band ----
    if (t == 0) {
        while (*(volatile unsigned*)&g_ready[m] == 0u) __nanosleep(128);
        s_cnt = 0; s_hi = 0;
    }
    __syncthreads();
    __threadfence();
    const unsigned Tlo = *(volatile unsigned*)&g_Tlo[m];
    const unsigned Thi = *(volatile unsigned*)&g_Thi[m];

    // ---- fused pass: mask write + hi count + band compaction ----
    const float4* __restrict__ in = m ? B : A;
    float4* __restrict__ dst = out + (size_t)m * (size_t)n4;
    unsigned hi = 0;
    const int stride = (gridDim.x >> 1) * blockDim.x;
    int i0 = (blockIdx.x >> 1) * blockDim.x + t;
    for (int i = i0; i < n4; i += 2 * stride) {
        int i2 = i + stride;
        float4 v0 = in[i];
        float4 v1 = (i2 < n4) ? in[i2] : make_float4(0.f, 0.f, 0.f, 0.f);
        float4 r0, r1;
        unsigned b0 = ((unsigned)i) << 2;
        unsigned b1 = ((unsigned)i2) << 2;
        unsigned k;

        k = abskey(v0.x); r0.x = (k >= Tlo) ? 1.0f : 0.0f; hi += (k >= Thi);
        if (k >= Tlo && k < Thi) { unsigned p = atomicAdd(&s_cnt, 1u); if (p < BLK_CAP) { s_idx[p] = b0;     s_key[p] = k; } }
        k = abskey(v0.y); r0.y = (k >= Tlo) ? 1.0f : 0.0f; hi += (k >= Thi);
        if (k >= Tlo && k < Thi) { unsigned p = atomicAdd(&s_cnt, 1u); if (p < BLK_CAP) { s_idx[p] = b0 + 1; s_key[p] = k; } }
        k = abskey(v0.z); r0.z = (k >= Tlo) ? 1.0f : 0.0f; hi += (k >= Thi);
        if (k >= Tlo && k < Thi) { unsigned p = atomicAdd(&s_cnt, 1u); if (p < BLK_CAP) { s_idx[p] = b0 + 2; s_key[p] = k; } }
        k = abskey(v0.w); r0.w = (k >= Tlo) ? 1.0f : 0.0f; hi += (k >= Thi);
        if (k >= Tlo && k < Thi) { unsigned p = atomicAdd(&s_cnt, 1u); if (p < BLK_CAP) { s_idx[p] = b0 + 3; s_key[p] = k; } }
        dst[i] = r0;

        if (i2 < n4) {
            k = abskey(v1.x); r1.x = (k >= Tlo) ? 1.0f : 0.0f; hi += (k >= Thi);
            if (k >= Tlo && k < Thi) { unsigned p = atomicAdd(&s_cnt, 1u); if (p < BLK_CAP) { s_idx[p] = b1;     s_key[p] = k; } }
            k = abskey(v1.y); r1.y = (k >= Tlo) ? 1.0f : 0.0f; hi += (k >= Thi);
            if (k >= Tlo && k < Thi) { unsigned p = atomicAdd(&s_cnt, 1u); if (p < BLK_CAP) { s_idx[p] = b1 + 1; s_key[p] = k; } }
            k = abskey(v1.z); r1.z = (k >= Tlo) ? 1.0f : 0.0f; hi += (k >= Thi);
            if (k >= Tlo && k < Thi) { unsigned p = atomicAdd(&s_cnt, 1u); if (p < BLK_CAP) { s_idx[p] = b1 + 2; s_key[p] = k; } }
            k = abskey(v1.w); r1.w = (k >= Tlo) ? 1.0f : 0.0f; hi += (k >= Thi);
            if (k >= Tlo && k < Thi) { unsigned p = atomicAdd(&s_cnt, 1u); if (p < BLK_CAP) { s_idx[p] = b1 + 3; s_key[p] = k; } }
            dst[i2] = r1;
        }
    }
    for (int off = 16; off > 0; off >>= 1) hi += __shfl_down_sync(0xFFFFFFFFu, hi, off);
    if ((t & 31) == 0 && hi) atomicAdd(&s_hi, hi);
    __syncthreads();
    if (t == 0) {
        if (s_hi) atomicAdd(&g_hiCnt[m], s_hi);
        unsigned c = s_cnt;
        if (c > BLK_CAP) { atomicExch(&g_fail[m], 1u); c = BLK_CAP; }
        s_cnt = c;
        s_base = atomicAdd(&g_cand_cnt[m], c);
    }
    __syncthreads();
    unsigned c = s_cnt, bpos = s_base;
    for (unsigned p = t; p < c; p += blockDim.x) {
        unsigned gp = bpos + p;
        if (gp < CAND_CAP) { g_cand_idx[m][gp] = s_idx[p]; g_cand_key[m][gp] = s_key[p]; }
    }
}

// Grid barrier over the nb blocks of matrix m (all co-resident: grid = 64).
__device__ __forceinline__ void gbar(int m, int ph, unsigned nb) {
    __syncthreads();
    if (threadIdx.x == 0) {
        __threadfence();
        atomicAdd(&g_bar[m][ph], 1u);
        while (*(volatile unsigned*)&g_bar[m][ph] < nb) __nanosleep(64);
        __threadfence();
    }
    __syncthreads();
}

// Single-block, slow, unconditionally-correct rescue (only on bound failure).
__device__ void rescue_block(const float* __restrict__ in, float* __restrict__ dst,
                             int n, unsigned target_top, unsigned* sh) {
    __shared__ unsigned r_lo, r_span, r_rank;
    const int t = threadIdx.x;
    if (t == 0) { r_lo = 0; r_span = 1u << 30; r_rank = (unsigned)n - target_top; }
    __syncthreads();
    while (r_span > 1) {
        unsigned lo = r_lo, span = r_span;
        unsigned s = (span > (unsigned)NCH) ? (unsigned)(32 - __clz(span - 1) - 11) : 0u;
        for (int i = t; i < NCH; i += 1024) sh[i] = 0;
        __syncthreads();
        for (int i = t; i < n; i += 1024) {
            unsigned d = abskey(in[i]) - lo;
            if (d < span) atomicAdd(&sh[d >> s], 1u);
        }
        __syncthreads();
        if (t == 0) {
            unsigned rank = r_rank, run = 0;
            for (int i = 0; i < NCH; i++) {
                unsigned cc = sh[i];
                if (rank < run + cc) { r_lo = lo + ((unsigned)i << s); r_span = 1u << s; r_rank = rank - run; break; }
                run += cc;
            }
        }
        __syncthreads();
    }
    unsigned T = r_lo, z = r_rank;
    for (int i = t; i < n; i += 1024) {
        unsigned k = abskey(in[i]);
        if (k != T) dst[i] = (k > T) ? 1.0f : 0.0f;
    }
    __syncthreads();
    if (t == 0) {
        unsigned seen = 0;
        for (int i = 0; i < n; i++)
            if (abskey(in[i]) == T) { dst[i] = (seen < z) ? 0.0f : 1.0f; seen++; }
    }
    __syncthreads();
}

__global__ void __launch_bounds__(1024)
refine_kernel(const float* __restrict__ A, const float* __restrict__ B,
              float* __restrict__ out, int n, unsigned target_top) {
    __shared__ unsigned sh[NCH];
    __shared__ unsigned s_sel, s_res;
    const int m = blockIdx.x & 1;
    const unsigned nb = gridDim.x >> 1;   // 32
    const unsigned bl = blockIdx.x >> 1;
    const int t = threadIdx.x;

    unsigned cnt_real = g_cand_cnt[m];
    unsigned cnt = min(cnt_real, CAND_CAP);
    unsigned hic = g_hiCnt[m];
    bool bad = (g_fail[m] != 0) || (cnt_real > CAND_CAP) ||
               (hic >= target_top) || (target_top - hic > cnt);
    unsigned rank = 0, lo = 0, span = 1;
    if (!bad) {
        unsigned keep = target_top - hic;
        rank = cnt - keep;
        lo = g_Tlo[m];
        span = g_Thi[m] - lo;
    }
    const unsigned* __restrict__ keys = g_cand_key[m];
    const unsigned* __restrict__ idxs = g_cand_idx[m];
    float* __restrict__ dst = out + (size_t)m * (size_t)n;

    // two narrowing stages (2048 bins each; 2048^2 = 4M >= any sane band)
    for (int st = 0; st < 2; st++) {
        bool active = (!bad) && (span > 1);
        unsigned s = 0;
        if (active) {
            s = (span > (unsigned)NCH) ? (unsigned)(32 - __clz(span - 1) - 11) : 0u;
            for (int i = t; i < NCH; i += 1024) sh[i] = 0;
            __syncthreads();
            unsigned stride = nb * 1024u;
            for (unsigned c = bl * 1024u + t; c < cnt; c += stride) {
                unsigned d = keys[c] - lo;
                if (d < span) atomicAdd(&sh[d >> s], 1u);
            }
            __syncthreads();
            for (int i = t; i < NCH; i += 1024) {
                unsigned v = sh[i];
                if (v) atomicAdd(&g_ch[m][st][i], v);
            }
        }
        gbar(m, st, nb);
        if (active) {
            unsigned l0 = g_ch[m][st][2 * t], l1 = g_ch[m][st][2 * t + 1];
            unsigned sum = l0 + l1;
            if (t == 0) { s_sel = 0; s_res = 0; }
            __syncthreads();
            sh[t] = sum;
            __syncthreads();
            for (int off = 1; off < 1024; off <<= 1) {
                unsigned x = (t >= off) ? sh[t - off] : 0u;
                __syncthreads();
                sh[t] += x;
                __syncthreads();
            }
            unsigned incl = sh[t], run = incl - sum;
            if (run <= rank && rank < run + l0)           { s_sel = 2 * t;     s_res = rank - run; }
            else if (run + l0 <= rank && rank < incl)     { s_sel = 2 * t + 1; s_res = rank - run - l0; }
            __syncthreads();
            lo += s_sel << s;
            span = 1u << s;
            rank = s_res;
            __syncthreads();
        }
    }
    if (!bad && span != 1) bad = true;  // paranoid: band too wide for 2 stages

    // final candidate pass
    if (!bad) {
        const unsigned T = lo;
        unsigned stride = nb * 1024u;
        for (unsigned c = bl * 1024u + t; c < cnt; c += stride) {
            unsigned k = keys[c];
            if (k < T) {
                dst[idxs[c]] = 0.0f;
            } else if (k == T) {
                unsigned p = atomicAdd(&g_eq_cnt[m], 1u);
                if (p < EQ_CAP) g_eq[m][p] = idxs[c];
            }
        }
    }
    gbar(m, 2, nb);
    unsigned eq = g_eq_cnt[m];
    if (!bad && eq > EQ_CAP) bad = true;
    if (bl == 0) {
        if (!bad) {
            unsigned z = rank;
            for (unsigned e = t; e < eq; e += 1024) {
                unsigned idx = g_eq[m][e];
                unsigned c2 = 0;
                for (unsigned q = 0; q < eq; q++) c2 += (g_eq[m][q] < idx) ? 1u : 0u;
                if (c2 < z) dst[idx] = 0.0f;
            }
        } else {
            rescue_block(m ? B : A, dst, n, target_top, sh);
        }
    }
    gbar(m, 3, nb);

    // self-clean for next replay's mega_kernel (g_bar reset there instead)
    for (unsigned i = bl * 1024u + t; i < NB1; i += nb * 1024u) g_shist[m][i] = 0;
    for (unsigned i = bl * 1024u + t; i < 2 * NCH; i += nb * 1024u) ((unsigned*)g_ch[m])[i] = 0;
    if (bl == 0 && t == 0) {
        g_sdone[m] = 0; g_ready[m] = 0; g_cand_cnt[m] = 0;
        g_hiCnt[m] = 0; g_fail[m] = 0; g_eq_cnt[m] = 0;
    }
}

extern "C" void kernel_launch(void* const* d_in, const int* in_sizes, int n_in,
                              void* d_out, int out_size) {
    const float* A = (const float*)d_in[0];
    const float* B = (const float*)d_in[1];
    float* out = (float*)d_out;

    int n = in_sizes[0];
    int n4 = n / 4;
    unsigned j = (unsigned)((1.0 - 0.1) * (double)n);  // mirrors int((1-k)*n)
    unsigned target_top = (unsigned)n - j;             // # of ones
    int n4s = n4 / 64;
    int chunk = n4s / 64;                              // float4s per sample block
    unsigned ns = (unsigned)chunk * 64u * 4u;          // sampled element count
    unsigned k_s = (unsigned)((double)target_top * (double)ns / (double)n);
    unsigned margin = 2048u;
    unsigned C_hi = k_s + margin; if (C_hi > ns) C_hi = ns;
    unsigned C_lo = (k_s > margin) ? (k_s - margin) : 1u;

    mega_kernel<<<2048, 512>>>((const float4*)A, (const float4*)B, (float4*)out,
                               n4, chunk, C_lo, C_hi);
    refine_kernel<<<64, 1024>>>(A, B, out, n, target_top);
}